// round 11
// baseline (speedup 1.0000x reference)
#include <cuda_runtime.h>
#include <math.h>

#define N_AG   512
#define H_DIM  128
#define XDIM   320
#define GDIM   512
#define KPOOL  2048
#define NS1    32
#define NS2    8
#define NCTA   296
#define NTHR   256
#define BCAP   120

typedef unsigned long long ull;

// ---------------- persistent device state ----------------
__device__ __align__(16) float g_obs[16 * 1024];
__device__ __align__(16) float g_hs[N_AG * H_DIM];
__device__ __align__(16) float g_cs[N_AG * H_DIM];
__device__ __align__(16) float g_X[N_AG * XDIM];       // [emb 0:64 | soc 64:192 | hs 192:320]
__device__ __align__(16) float g_grid[N_AG * KPOOL];
__device__ __align__(16) float g_socpart[NS1 * N_AG * H_DIM];
__device__ __align__(16) float g_gpart[NS2 * N_AG * GDIM];
__device__ __align__(16) float g_WpT[KPOOL * H_DIM];   // W_pool^T, k-major
__device__ __align__(16) float g_WcT[2 * XDIM * GDIM]; // Wcat^T, k-major
__device__ __align__(16) float g_bsum[2 * GDIM];
__device__ float g_curr[N_AG * 2];
__device__ float g_prev[N_AG * 2];
__device__ unsigned g_leaf[8 * 32];
__device__ unsigned g_root;

__device__ __forceinline__ float sigf(float x) { return 1.0f / (1.0f + expf(-x)); }

__device__ __forceinline__ ull pk2(float x, float y) {
    ull r; asm("mov.b64 %0, {%1, %2};" : "=l"(r) : "f"(x), "f"(y)); return r;
}
__device__ __forceinline__ void upk2(ull v, float& x, float& y) {
    asm("mov.b64 {%0, %1}, %2;" : "=f"(x), "=f"(y) : "l"(v));
}
__device__ __forceinline__ ull fma2(ull a, ull b, ull c) {
    ull d; asm("fma.rn.f32x2 %0, %1, %2, %3;" : "=l"(d) : "l"(a), "l"(b), "l"(c)); return d;
}

// ---------------- shared memory ----------------
struct SPool {
    int bkt[2][16][BCAP];
    int bcnt[2][16];
    int ovf[2][512];
    int ovfcnt[2];
};
struct SGemm {
    float As[2][8][65];
    ull   Bs[2][8][64];
};
union SU { SPool pool; SGemm g; float sh[2][H_DIM]; };

// ---------------- two-level grid barrier ----------------
__device__ __forceinline__ void grid_bar(int barno) {
    __syncthreads();
    if (threadIdx.x == 0) {
        unsigned old;
        unsigned* leaf = &g_leaf[(blockIdx.x & 7) * 32];
        asm volatile("atom.add.acq_rel.gpu.u32 %0, [%1], 1;"
                     : "=r"(old) : "l"(leaf) : "memory");
        if (old == 37u * (unsigned)barno - 1u) {
            unsigned dummy;
            asm volatile("atom.add.release.gpu.u32 %0, [%1], 1;"
                         : "=r"(dummy) : "l"(&g_root) : "memory");
        }
        unsigned tgt = 8u * (unsigned)barno, v;
        while (true) {
            asm volatile("ld.acquire.gpu.u32 %0, [%1];"
                         : "=r"(v) : "l"(&g_root) : "memory");
            if (v >= tgt) break;
            __nanosleep(32);
        }
    }
    __syncthreads();
}

// ---------------- 64x128 GEMM tile (A from global, double-buffered) ----------------
__device__ __forceinline__ void mm64(SGemm& S,
                                     const float* __restrict__ A, int lda, int r0, int koff,
                                     const float* __restrict__ Bt, int ldbt, int col0,
                                     int nchunks, float* __restrict__ C, int ldc)
{
    int tid = threadIdx.x;
    int tr = tid >> 4, tc = tid & 15;
    int ar = tid >> 1, ak4 = (tid & 1) * 4;          // tid<128: A 64 rows x 8k
    int bk = tid >> 5, bc4 = (tid & 31) * 4;

    ull acc[4][4];
#pragma unroll
    for (int i = 0; i < 4; i++)
#pragma unroll
        for (int j = 0; j < 4; j++) acc[i][j] = pk2(0.f, 0.f);

    float4 av, bv;
    if (tid < 128) av = *(const float4*)&A[(r0 + ar) * lda + koff + ak4];
    bv = *(const float4*)&Bt[(koff + bk) * ldbt + col0 + bc4];
    if (tid < 128) {
        S.As[0][ak4 + 0][ar] = av.x; S.As[0][ak4 + 1][ar] = av.y;
        S.As[0][ak4 + 2][ar] = av.z; S.As[0][ak4 + 3][ar] = av.w;
    }
    S.Bs[0][bk][(bc4 >> 1)]     = pk2(bv.x, bv.y);
    S.Bs[0][bk][(bc4 >> 1) + 1] = pk2(bv.z, bv.w);
    __syncthreads();

    for (int c = 0; c < nchunks; c++) {
        int cur = c & 1;
        bool has = (c + 1 < nchunks);
        if (has) {
            if (tid < 128) av = *(const float4*)&A[(r0 + ar) * lda + koff + (c + 1) * 8 + ak4];
            bv = *(const float4*)&Bt[(koff + (c + 1) * 8 + bk) * ldbt + col0 + bc4];
        }
#pragma unroll
        for (int k = 0; k < 8; k++) {
            ull aa[4], b[4];
#pragma unroll
            for (int i = 0; i < 4; i++) {
                float a = S.As[cur][k][tr * 4 + i];
                aa[i] = pk2(a, a);
            }
#pragma unroll
            for (int j = 0; j < 4; j++) b[j] = S.Bs[cur][k][tc + 16 * j];
#pragma unroll
            for (int i = 0; i < 4; i++)
#pragma unroll
                for (int j = 0; j < 4; j++) acc[i][j] = fma2(aa[i], b[j], acc[i][j]);
        }
        __syncthreads();
        if (has) {
            int nxt = cur ^ 1;
            if (tid < 128) {
                S.As[nxt][ak4 + 0][ar] = av.x; S.As[nxt][ak4 + 1][ar] = av.y;
                S.As[nxt][ak4 + 2][ar] = av.z; S.As[nxt][ak4 + 3][ar] = av.w;
            }
            S.Bs[nxt][bk][(bc4 >> 1)]     = pk2(bv.x, bv.y);
            S.Bs[nxt][bk][(bc4 >> 1) + 1] = pk2(bv.z, bv.w);
            __syncthreads();
        }
    }

#pragma unroll
    for (int i = 0; i < 4; i++) {
        int row = r0 + tr * 4 + i;
#pragma unroll
        for (int j = 0; j < 4; j++) {
            float x, y;
            upk2(acc[i][j], x, y);
            *(float2*)&C[row * ldc + col0 + 2 * (tc + 16 * j)] = make_float2(x, y);
        }
    }
}

// ---------------- setup ----------------
__global__ void setup_kernel(const float* __restrict__ observed, int T,
                             const float* __restrict__ W_pool,
                             const float* __restrict__ Wih_e, const float* __restrict__ bih_e,
                             const float* __restrict__ Whh_e, const float* __restrict__ bhh_e,
                             const float* __restrict__ Wih_d, const float* __restrict__ bih_d,
                             const float* __restrict__ Whh_d, const float* __restrict__ bhh_d)
{
    int gtid = blockIdx.x * blockDim.x + threadIdx.x;
    int nth  = gridDim.x * blockDim.x;

    if (gtid == 0) g_root = 0u;
    if (gtid < 8 * 32) g_leaf[gtid] = 0u;

    for (int i = gtid; i < N_AG; i += nth) {
        int firstv = -1;
        for (int t = 0; t < T; t++) {
            float x = observed[t * 1024 + i * 2], y = observed[t * 1024 + i * 2 + 1];
            if (isfinite(x) && isfinite(y)) { firstv = t; break; }
        }
        int last = -1;
        for (int t = 0; t < T; t++) {
            float x = observed[t * 1024 + i * 2], y = observed[t * 1024 + i * 2 + 1];
            if (isfinite(x) && isfinite(y)) last = t;
            int take = (last >= 0) ? last : firstv;
            float ox = 0.0f, oy = 0.0f;
            if (firstv >= 0) {
                ox = observed[take * 1024 + i * 2];
                oy = observed[take * 1024 + i * 2 + 1];
            }
            g_obs[t * 1024 + i * 2]     = ox;
            g_obs[t * 1024 + i * 2 + 1] = oy;
        }
    }
    for (int idx = gtid; idx < N_AG * H_DIM; idx += nth) {
        g_hs[idx] = 0.0f; g_cs[idx] = 0.0f;
        g_X[(idx >> 7) * XDIM + 192 + (idx & 127)] = 0.0f;
    }
    for (int idx = gtid; idx < KPOOL * H_DIM; idx += nth) {
        int k = idx / H_DIM, n = idx - k * H_DIM;
        g_WpT[idx] = W_pool[n * KPOOL + k];
    }
    for (int idx = gtid; idx < XDIM * GDIM; idx += nth) {
        int k = idx / GDIM, g = idx - k * GDIM;
        g_WcT[idx]               = (k < 192) ? Wih_e[g * 192 + k] : Whh_e[g * 128 + (k - 192)];
        g_WcT[XDIM * GDIM + idx] = (k < 192) ? Wih_d[g * 192 + k] : Whh_d[g * 128 + (k - 192)];
    }
    for (int g = gtid; g < GDIM; g += nth) {
        g_bsum[g]        = bih_e[g] + bhh_e[g];
        g_bsum[GDIM + g] = bih_d[g] + bhh_d[g];
    }
}

// ---------------- persistent kernel ----------------
__global__ void __launch_bounds__(NTHR, 2)
main_kernel(int T, int npred,
            const float* __restrict__ W_pos, const float* __restrict__ b_pos,
            const float* __restrict__ b_pool,
            const float* __restrict__ W_out, const float* __restrict__ b_out,
            float* __restrict__ out)
{
    __shared__ SU sm;
    int tid = threadIdx.x;
    int blk = blockIdx.x;
    int barno = 0;
    int nsteps = (T - 1) + npred;
    const float NEG_INF = -__int_as_float(0x7f800000);

    for (int s = 0; s < nsteps; s++) {
        bool dec = (s >= T - 1);
        int d = s - (T - 1);
        const float* posbuf  = dec ? ((d == 0) ? g_obs + (T - 1) * 1024 : g_curr)
                                   : g_obs + (s + 1) * 1024;
        const float* prevbuf = dec ? ((d == 0) ? g_obs + (T - 1) * 1024 : g_prev)
                                   : g_obs + s * 1024;
        int wsel = dec ? 1 : 0;

        // ======== phase 1: pool (256 CTAs, 2 agents each) ========
        if (blk < 256) {
            int half = tid >> 7, t = tid & 127;
            int i = blk + 256 * half;
            int* bc = sm.pool.bcnt[half];

            if (t < 16) bc[t] = 0;
            if (t == 0) sm.pool.ovfcnt[half] = 0;
            float px = posbuf[i * 2], py = posbuf[i * 2 + 1];
            __syncthreads();

#pragma unroll
            for (int q = 0; q < 4; q++) {
                int j = t + q * 128;
                float dx = posbuf[j * 2] - px, dy = posbuf[j * 2 + 1] - py;
                if (j != i && fabsf(dx) <= 1.f && fabsf(dy) <= 1.f) {
                    int gx = min(3, max(0, (int)floorf((dx + 1.f) * 2.f)));
                    int gy = min(3, max(0, (int)floorf((dy + 1.f) * 2.f)));
                    int c = gx * 4 + gy;
                    int slot = atomicAdd(&bc[c], 1);
                    if (slot < BCAP) sm.pool.bkt[half][c][slot] = j;
                    else {
                        int o = atomicAdd(&sm.pool.ovfcnt[half], 1);
                        sm.pool.ovf[half][o] = (j << 4) | c;
                    }
                }
            }
            __syncthreads();
            int ocnt = sm.pool.ovfcnt[half];
#pragma unroll 1
            for (int c = 0; c < 16; c++) {
                int nc = min(bc[c], BCAP);
                const int* bl = sm.pool.bkt[half][c];
                float m = NEG_INF;
                int e = 0;
                for (; e + 8 <= nc; e += 8) {
                    float v0 = g_hs[bl[e] * 128 + t];
                    float v1 = g_hs[bl[e + 1] * 128 + t];
                    float v2 = g_hs[bl[e + 2] * 128 + t];
                    float v3 = g_hs[bl[e + 3] * 128 + t];
                    float v4 = g_hs[bl[e + 4] * 128 + t];
                    float v5 = g_hs[bl[e + 5] * 128 + t];
                    float v6 = g_hs[bl[e + 6] * 128 + t];
                    float v7 = g_hs[bl[e + 7] * 128 + t];
                    m = fmaxf(m, fmaxf(fmaxf(fmaxf(v0, v1), fmaxf(v2, v3)),
                                       fmaxf(fmaxf(v4, v5), fmaxf(v6, v7))));
                }
                for (; e < nc; e++) m = fmaxf(m, g_hs[bl[e] * 128 + t]);
                for (int o = 0; o < ocnt; o++) {
                    int pv = sm.pool.ovf[half][o];
                    if ((pv & 15) == c) m = fmaxf(m, g_hs[(pv >> 4) * 128 + t]);
                }
                g_grid[i * KPOOL + c * 128 + t] = (m == NEG_INF) ? 0.f : m;
            }
            if (t < 64) {
                float vx = px - prevbuf[i * 2], vy = py - prevbuf[i * 2 + 1];
                g_X[i * XDIM + t] = fmaxf(b_pos[t] + vx * W_pos[t * 2] + vy * W_pos[t * 2 + 1], 0.f);
            }
        }
        grid_bar(++barno);

        // ======== phase 2: gemm1 partials (256 tiles: 8 rb x 32 ks, K=64) ========
        if (blk < 256) {
            int rb = blk & 7, ks = blk >> 3;
            mm64(sm.g, g_grid, KPOOL, rb * 64, ks * 64,
                 g_WpT, H_DIM, 0, 8,
                 g_socpart + ks * (N_AG * H_DIM), H_DIM);
        }
        grid_bar(++barno);

        // ======== phase 3: red1 (sum 32 + bias + relu -> X soc) ========
        {
            int gt = blk * NTHR + tid;
            if (gt < N_AG * H_DIM) {
                int row = gt >> 7, h = gt & 127;
                float ssum = b_pool[h];
#pragma unroll
                for (int p = 0; p < NS1; p++)
                    ssum += g_socpart[p * (N_AG * H_DIM) + row * H_DIM + h];
                g_X[row * XDIM + 64 + h] = fmaxf(ssum, 0.f);
            }
        }
        grid_bar(++barno);

        // ======== phase 4: gemm2 partials (256 tiles: 8 rb x 4 cb x 8 ks, K=40) ========
        if (blk < 256) {
            int rb = blk & 7, cb = (blk >> 3) & 3, ks = blk >> 5;
            mm64(sm.g, g_X, XDIM, rb * 64, ks * 40,
                 g_WcT + wsel * XDIM * GDIM, GDIM, cb * 128, 5,
                 g_gpart + ks * (N_AG * GDIM), GDIM);
        }
        grid_bar(++barno);

        // ======== phase 5: red2 + LSTM + hs->X + decoder out ========
        {
            int gid = blk * NTHR + tid;
            if (gid < N_AG * H_DIM) {
                int row = gid >> 7, h = gid & 127;
                int rl = tid >> 7;
                const float* bs = g_bsum + wsel * GDIM;
                float gg[4];
#pragma unroll
                for (int q = 0; q < 4; q++) {
                    float ssum = bs[q * 128 + h];
#pragma unroll
                    for (int p = 0; p < NS2; p++)
                        ssum += g_gpart[p * (N_AG * GDIM) + row * GDIM + q * 128 + h];
                    gg[q] = ssum;
                }
                float c  = g_cs[row * H_DIM + h];
                float c2 = sigf(gg[1]) * c + sigf(gg[0]) * tanhf(gg[2]);
                float h2 = sigf(gg[3]) * tanhf(c2);
                g_cs[row * H_DIM + h] = c2;
                g_hs[row * H_DIM + h] = h2;
                g_X[row * XDIM + 192 + h] = h2;
                if (dec) {
                    sm.sh[rl][h] = h2;
                    __syncthreads();
                    if (tid < 128) {
                        int w = tid >> 5, lane = tid & 31;
                        int rl2 = w >> 1, comp = w & 1;
                        int row2 = blk * 2 + rl2;
                        float4 hv = *(const float4*)&sm.sh[rl2][lane * 4];
                        float4 wv = *(const float4*)&W_out[comp * H_DIM + lane * 4];
                        float sv = hv.x * wv.x + hv.y * wv.y + hv.z * wv.z + hv.w * wv.w;
#pragma unroll
                        for (int o = 16; o > 0; o >>= 1) sv += __shfl_down_sync(0xffffffffu, sv, o);
                        if (lane == 0) {
                            float pv = posbuf[row2 * 2 + comp];
                            float nx = pv + sv + b_out[comp];
                            out[d * 1024 + row2 * 2 + comp] = nx;
                            g_prev[row2 * 2 + comp] = pv;
                            g_curr[row2 * 2 + comp] = nx;
                        }
                    }
                }
            }
        }
        grid_bar(++barno);
    }
}

// ---------------- launch ----------------
extern "C" void kernel_launch(void* const* d_in, const int* in_sizes, int n_in,
                              void* d_out, int out_size)
{
    const float* observed = (const float*)d_in[0];
    const float* W_pos    = (const float*)d_in[1];
    const float* b_pos    = (const float*)d_in[2];
    const float* W_pool   = (const float*)d_in[3];
    const float* b_pool   = (const float*)d_in[4];
    const float* Wih_e    = (const float*)d_in[5];
    const float* bih_e    = (const float*)d_in[6];
    const float* Whh_e    = (const float*)d_in[7];
    const float* bhh_e    = (const float*)d_in[8];
    const float* Wih_d    = (const float*)d_in[9];
    const float* bih_d    = (const float*)d_in[10];
    const float* Whh_d    = (const float*)d_in[11];
    const float* bhh_d    = (const float*)d_in[12];
    const float* W_out    = (const float*)d_in[13];
    const float* b_out    = (const float*)d_in[14];
    float* out = (float*)d_out;

    int T = in_sizes[0] / (N_AG * 2);
    if (T > 16) T = 16;
    int npred = out_size / (N_AG * 2);

    setup_kernel<<<64, 256>>>(observed, T, W_pool, Wih_e, bih_e, Whh_e, bhh_e,
                              Wih_d, bih_d, Whh_d, bhh_d);
    main_kernel<<<NCTA, NTHR>>>(T, npred, W_pos, b_pos, b_pool, W_out, b_out, out);
}

// round 13
// speedup vs baseline: 1.6388x; 1.6388x over previous
#include <cuda_runtime.h>
#include <math.h>

#define N_AG   512
#define H_DIM  128
#define XDIM   320
#define GDIM   512
#define KPOOL  2048
#define NS1    32
#define NS2    8
#define NCTA   148
#define NTHR   512
#define BCAP   120

typedef unsigned long long ull;

// ---------------- persistent device state ----------------
__device__ __align__(16) float g_obs[16 * 1024];
__device__ __align__(16) float g_hs[N_AG * H_DIM];
__device__ __align__(16) float g_cs[N_AG * H_DIM];
__device__ __align__(16) float g_X[N_AG * XDIM];       // [emb 0:64 | soc 64:192 | hs 192:320]
__device__ __align__(16) float g_grid[N_AG * KPOOL];
__device__ __align__(16) float g_socpart[NS1 * N_AG * H_DIM];
__device__ __align__(16) float g_gpart[NS2 * N_AG * GDIM];
__device__ __align__(16) float g_WpT[KPOOL * H_DIM];   // W_pool^T, k-major
__device__ __align__(16) float g_WcT[2 * XDIM * GDIM]; // Wcat^T, k-major
__device__ __align__(16) float g_bsum[2 * GDIM];
__device__ float g_curr[N_AG * 2];
__device__ float g_prev[N_AG * 2];
__device__ unsigned g_root;

__device__ __forceinline__ float sigf(float x) { return 1.0f / (1.0f + expf(-x)); }

__device__ __forceinline__ ull pk2(float x, float y) {
    ull r; asm("mov.b64 %0, {%1, %2};" : "=l"(r) : "f"(x), "f"(y)); return r;
}
__device__ __forceinline__ void upk2(ull v, float& x, float& y) {
    asm("mov.b64 {%0, %1}, %2;" : "=f"(x), "=f"(y) : "l"(v));
}
__device__ __forceinline__ ull fma2(ull a, ull b, ull c) {
    ull d; asm("fma.rn.f32x2 %0, %1, %2, %3;" : "=l"(d) : "l"(a), "l"(b), "l"(c)); return d;
}

// ---------------- shared memory ----------------
struct SPool {                          // 4 agent-groups per CTA
    int bkt[4][16][BCAP];
    int bcnt[4][16];
    int ovf[4][512];
    int ovfcnt[4];
};
struct SGemm {                          // 128-row tile, 512 threads
    float As[2][8][130];                // A scalars [k][row], padded
    ull   Bs[2][8][64];                 // B col-pairs [k][cpair]
};
union SU { SPool pool; SGemm g; float sh[4][H_DIM]; };

// ---------------- single-level grid barrier (148 arrivals) ----------------
__device__ __forceinline__ void grid_bar(int barno) {
    __syncthreads();
    if (threadIdx.x == 0) {
        unsigned old;
        asm volatile("atom.add.acq_rel.gpu.u32 %0, [%1], 1;"
                     : "=r"(old) : "l"(&g_root) : "memory");
        unsigned tgt = (unsigned)NCTA * (unsigned)barno;
        if (old + 1u < tgt) {
            unsigned v;
            do {
                __nanosleep(16);
                asm volatile("ld.acquire.gpu.u32 %0, [%1];"
                             : "=r"(v) : "l"(&g_root) : "memory");
            } while (v < tgt);
        }
    }
    __syncthreads();
}

// ---------------- 128x128 GEMM tile, 512 threads, double-buffered ----------------
__device__ __forceinline__ void mm128(SGemm& S,
                                      const float* __restrict__ A, int lda, int r0, int koff,
                                      const float* __restrict__ Bt, int ldbt, int col0,
                                      int nchunks, float* __restrict__ C, int ldc)
{
    int tid = threadIdx.x;
    int tr = tid >> 4, tc = tid & 15;                 // tr 0..31 (4 rows), tc 0..15 (4 ull cols)
    bool isA = tid < 256;
    int ar = tid >> 1, ak4 = (tid & 1) * 4;           // A: 128 rows x 8k (256 thr)
    int bt = tid - 256;
    int bk = bt >> 5, bc4 = (bt & 31) * 4;            // B: 8k x 128 cols (256 thr)

    ull acc[4][4];
#pragma unroll
    for (int i = 0; i < 4; i++)
#pragma unroll
        for (int j = 0; j < 4; j++) acc[i][j] = pk2(0.f, 0.f);

    float4 av, bv;
    if (isA) av = *(const float4*)&A[(r0 + ar) * lda + koff + ak4];
    else     bv = *(const float4*)&Bt[(koff + bk) * ldbt + col0 + bc4];
    if (isA) {
        S.As[0][ak4 + 0][ar] = av.x; S.As[0][ak4 + 1][ar] = av.y;
        S.As[0][ak4 + 2][ar] = av.z; S.As[0][ak4 + 3][ar] = av.w;
    } else {
        S.Bs[0][bk][(bc4 >> 1)]     = pk2(bv.x, bv.y);
        S.Bs[0][bk][(bc4 >> 1) + 1] = pk2(bv.z, bv.w);
    }
    __syncthreads();

    for (int c = 0; c < nchunks; c++) {
        int cur = c & 1;
        bool has = (c + 1 < nchunks);
        if (has) {
            if (isA) av = *(const float4*)&A[(r0 + ar) * lda + koff + (c + 1) * 8 + ak4];
            else     bv = *(const float4*)&Bt[(koff + (c + 1) * 8 + bk) * ldbt + col0 + bc4];
        }
#pragma unroll
        for (int k = 0; k < 8; k++) {
            ull aa[4], b[4];
#pragma unroll
            for (int i = 0; i < 4; i++) {
                float a = S.As[cur][k][tr * 4 + i];
                aa[i] = pk2(a, a);
            }
#pragma unroll
            for (int j = 0; j < 4; j++) b[j] = S.Bs[cur][k][tc + 16 * j];
#pragma unroll
            for (int i = 0; i < 4; i++)
#pragma unroll
                for (int j = 0; j < 4; j++) acc[i][j] = fma2(aa[i], b[j], acc[i][j]);
        }
        __syncthreads();
        if (has) {
            int nxt = cur ^ 1;
            if (isA) {
                S.As[nxt][ak4 + 0][ar] = av.x; S.As[nxt][ak4 + 1][ar] = av.y;
                S.As[nxt][ak4 + 2][ar] = av.z; S.As[nxt][ak4 + 3][ar] = av.w;
            } else {
                S.Bs[nxt][bk][(bc4 >> 1)]     = pk2(bv.x, bv.y);
                S.Bs[nxt][bk][(bc4 >> 1) + 1] = pk2(bv.z, bv.w);
            }
            __syncthreads();
        }
    }

#pragma unroll
    for (int i = 0; i < 4; i++) {
        int row = r0 + tr * 4 + i;
#pragma unroll
        for (int j = 0; j < 4; j++) {
            float x, y;
            upk2(acc[i][j], x, y);
            *(float2*)&C[row * ldc + col0 + 2 * (tc + 16 * j)] = make_float2(x, y);
        }
    }
}

// ---------------- setup ----------------
__global__ void setup_kernel(const float* __restrict__ observed, int T,
                             const float* __restrict__ W_pool,
                             const float* __restrict__ Wih_e, const float* __restrict__ bih_e,
                             const float* __restrict__ Whh_e, const float* __restrict__ bhh_e,
                             const float* __restrict__ Wih_d, const float* __restrict__ bih_d,
                             const float* __restrict__ Whh_d, const float* __restrict__ bhh_d)
{
    int gtid = blockIdx.x * blockDim.x + threadIdx.x;
    int nth  = gridDim.x * blockDim.x;

    if (gtid == 0) g_root = 0u;

    for (int i = gtid; i < N_AG; i += nth) {
        int firstv = -1;
        for (int t = 0; t < T; t++) {
            float x = observed[t * 1024 + i * 2], y = observed[t * 1024 + i * 2 + 1];
            if (isfinite(x) && isfinite(y)) { firstv = t; break; }
        }
        int last = -1;
        for (int t = 0; t < T; t++) {
            float x = observed[t * 1024 + i * 2], y = observed[t * 1024 + i * 2 + 1];
            if (isfinite(x) && isfinite(y)) last = t;
            int take = (last >= 0) ? last : firstv;
            float ox = 0.0f, oy = 0.0f;
            if (firstv >= 0) {
                ox = observed[take * 1024 + i * 2];
                oy = observed[take * 1024 + i * 2 + 1];
            }
            g_obs[t * 1024 + i * 2]     = ox;
            g_obs[t * 1024 + i * 2 + 1] = oy;
        }
    }
    for (int idx = gtid; idx < N_AG * H_DIM; idx += nth) {
        g_hs[idx] = 0.0f; g_cs[idx] = 0.0f;
        g_X[(idx >> 7) * XDIM + 192 + (idx & 127)] = 0.0f;
    }
    for (int idx = gtid; idx < KPOOL * H_DIM; idx += nth) {
        int k = idx / H_DIM, n = idx - k * H_DIM;
        g_WpT[idx] = W_pool[n * KPOOL + k];
    }
    for (int idx = gtid; idx < XDIM * GDIM; idx += nth) {
        int k = idx / GDIM, g = idx - k * GDIM;
        g_WcT[idx]               = (k < 192) ? Wih_e[g * 192 + k] : Whh_e[g * 128 + (k - 192)];
        g_WcT[XDIM * GDIM + idx] = (k < 192) ? Wih_d[g * 192 + k] : Whh_d[g * 128 + (k - 192)];
    }
    for (int g = gtid; g < GDIM; g += nth) {
        g_bsum[g]        = bih_e[g] + bhh_e[g];
        g_bsum[GDIM + g] = bih_d[g] + bhh_d[g];
    }
}

// ---------------- persistent kernel: 148 CTAs x 512 thr, 1 CTA/SM ----------------
__global__ void __launch_bounds__(NTHR, 1)
main_kernel(int T, int npred,
            const float* __restrict__ W_pos, const float* __restrict__ b_pos,
            const float* __restrict__ b_pool,
            const float* __restrict__ W_out, const float* __restrict__ b_out,
            float* __restrict__ out)
{
    __shared__ SU sm;
    int tid = threadIdx.x;
    int blk = blockIdx.x;
    int barno = 0;
    int nsteps = (T - 1) + npred;
    const float NEG_INF = -__int_as_float(0x7f800000);

    for (int s = 0; s < nsteps; s++) {
        bool dec = (s >= T - 1);
        int d = s - (T - 1);
        const float* posbuf  = dec ? ((d == 0) ? g_obs + (T - 1) * 1024 : g_curr)
                                   : g_obs + (s + 1) * 1024;
        const float* prevbuf = dec ? ((d == 0) ? g_obs + (T - 1) * 1024 : g_prev)
                                   : g_obs + s * 1024;
        int wsel = dec ? 1 : 0;

        // ======== phase 1: pool (4 agent-groups of 128 threads per CTA) ========
        {
            int grp = tid >> 7, t = tid & 127;
            int i = blk + 148 * grp;               // agent for this group
            bool act = (i < N_AG);
            int* bc = sm.pool.bcnt[grp];
            float px = 0.f, py = 0.f;

            if (act) {
                if (t < 16) bc[t] = 0;
                if (t == 0) sm.pool.ovfcnt[grp] = 0;
                px = posbuf[i * 2]; py = posbuf[i * 2 + 1];
            }
            __syncthreads();

            if (act) {
#pragma unroll
                for (int q = 0; q < 4; q++) {
                    int j = t + q * 128;
                    float dx = posbuf[j * 2] - px, dy = posbuf[j * 2 + 1] - py;
                    if (j != i && fabsf(dx) <= 1.f && fabsf(dy) <= 1.f) {
                        int gx = min(3, max(0, (int)floorf((dx + 1.f) * 2.f)));
                        int gy = min(3, max(0, (int)floorf((dy + 1.f) * 2.f)));
                        int c = gx * 4 + gy;
                        int slot = atomicAdd(&bc[c], 1);
                        if (slot < BCAP) sm.pool.bkt[grp][c][slot] = j;
                        else {
                            int o = atomicAdd(&sm.pool.ovfcnt[grp], 1);
                            sm.pool.ovf[grp][o] = (j << 4) | c;
                        }
                    }
                }
            }
            __syncthreads();

            if (act) {
                int ocnt = sm.pool.ovfcnt[grp];
#pragma unroll 1
                for (int c = 0; c < 16; c++) {
                    int nc = min(bc[c], BCAP);
                    const int* bl = sm.pool.bkt[grp][c];
                    float m = NEG_INF;
                    int e = 0;
                    for (; e + 8 <= nc; e += 8) {
                        float v0 = g_hs[bl[e] * 128 + t];
                        float v1 = g_hs[bl[e + 1] * 128 + t];
                        float v2 = g_hs[bl[e + 2] * 128 + t];
                        float v3 = g_hs[bl[e + 3] * 128 + t];
                        float v4 = g_hs[bl[e + 4] * 128 + t];
                        float v5 = g_hs[bl[e + 5] * 128 + t];
                        float v6 = g_hs[bl[e + 6] * 128 + t];
                        float v7 = g_hs[bl[e + 7] * 128 + t];
                        m = fmaxf(m, fmaxf(fmaxf(fmaxf(v0, v1), fmaxf(v2, v3)),
                                           fmaxf(fmaxf(v4, v5), fmaxf(v6, v7))));
                    }
                    for (; e < nc; e++) m = fmaxf(m, g_hs[bl[e] * 128 + t]);
                    for (int o = 0; o < ocnt; o++) {
                        int pv = sm.pool.ovf[grp][o];
                        if ((pv & 15) == c) m = fmaxf(m, g_hs[(pv >> 4) * 128 + t]);
                    }
                    g_grid[i * KPOOL + c * 128 + t] = (m == NEG_INF) ? 0.f : m;
                }
                if (t < 64) {
                    float vx = px - prevbuf[i * 2], vy = py - prevbuf[i * 2 + 1];
                    g_X[i * XDIM + t] = fmaxf(b_pos[t] + vx * W_pos[t * 2] + vy * W_pos[t * 2 + 1], 0.f);
                }
            }
        }
        grid_bar(++barno);

        // ======== phase 2: gemm1 partials (128 tiles: 4 rb x 32 ks, 128x128xK64) ========
        if (blk < 128) {
            int rb = blk & 3, ks = blk >> 2;
            mm128(sm.g, g_grid, KPOOL, rb * 128, ks * 64,
                  g_WpT, H_DIM, 0, 8,
                  g_socpart + ks * (N_AG * H_DIM), H_DIM);
        }
        grid_bar(++barno);

        // ======== phase 3: red1 (sum 32 + bias + relu -> X soc) ========
        {
            int gt = blk * NTHR + tid;
            if (gt < N_AG * H_DIM) {
                int row = gt >> 7, h = gt & 127;
                float ssum = b_pool[h];
#pragma unroll
                for (int p = 0; p < NS1; p++)
                    ssum += g_socpart[p * (N_AG * H_DIM) + row * H_DIM + h];
                g_X[row * XDIM + 64 + h] = fmaxf(ssum, 0.f);
            }
        }
        grid_bar(++barno);

        // ======== phase 4: gemm2 partials (128 tiles: 4 rb x 4 cb x 8 ks, K=40) ========
        if (blk < 128) {
            int rb = blk & 3, cb = (blk >> 2) & 3, ks = blk >> 4;
            mm128(sm.g, g_X, XDIM, rb * 128, ks * 40,
                  g_WcT + wsel * XDIM * GDIM, GDIM, cb * 128, 5,
                  g_gpart + ks * (N_AG * GDIM), GDIM);
        }
        grid_bar(++barno);

        // ======== phase 5: red2 + LSTM + hs->X + decoder out ========
        {
            int gid = blk * NTHR + tid;
            bool act = (gid < N_AG * H_DIM);       // blk < 128
            int row = gid >> 7, h = gid & 127;
            int rl = tid >> 7;                     // 4 rows per CTA
            if (act) {
                const float* bs = g_bsum + wsel * GDIM;
                float gg[4];
#pragma unroll
                for (int q = 0; q < 4; q++) {
                    float ssum = bs[q * 128 + h];
#pragma unroll
                    for (int p = 0; p < NS2; p++)
                        ssum += g_gpart[p * (N_AG * GDIM) + row * GDIM + q * 128 + h];
                    gg[q] = ssum;
                }
                float c  = g_cs[row * H_DIM + h];
                float c2 = sigf(gg[1]) * c + sigf(gg[0]) * tanhf(gg[2]);
                float h2 = sigf(gg[3]) * tanhf(c2);
                g_cs[row * H_DIM + h] = c2;
                g_hs[row * H_DIM + h] = h2;
                g_X[row * XDIM + 192 + h] = h2;
                if (dec) sm.sh[rl][h] = h2;
            }
            if (dec) {
                __syncthreads();
                if (blk < 128 && tid < 256) {      // 8 warps: 4 rows x 2 comps
                    int w = tid >> 5, lane = tid & 31;
                    int rl2 = w >> 1, comp = w & 1;
                    int row2 = blk * 4 + rl2;
                    float4 hv = *(const float4*)&sm.sh[rl2][lane * 4];
                    float4 wv = *(const float4*)&W_out[comp * H_DIM + lane * 4];
                    float sv = hv.x * wv.x + hv.y * wv.y + hv.z * wv.z + hv.w * wv.w;
#pragma unroll
                    for (int o = 16; o > 0; o >>= 1) sv += __shfl_down_sync(0xffffffffu, sv, o);
                    if (lane == 0) {
                        float pv = posbuf[row2 * 2 + comp];
                        float nx = pv + sv + b_out[comp];
                        out[d * 1024 + row2 * 2 + comp] = nx;
                        g_prev[row2 * 2 + comp] = pv;
                        g_curr[row2 * 2 + comp] = nx;
                    }
                }
            }
        }
        grid_bar(++barno);
    }
}

// ---------------- launch ----------------
extern "C" void kernel_launch(void* const* d_in, const int* in_sizes, int n_in,
                              void* d_out, int out_size)
{
    const float* observed = (const float*)d_in[0];
    const float* W_pos    = (const float*)d_in[1];
    const float* b_pos    = (const float*)d_in[2];
    const float* W_pool   = (const float*)d_in[3];
    const float* b_pool   = (const float*)d_in[4];
    const float* Wih_e    = (const float*)d_in[5];
    const float* bih_e    = (const float*)d_in[6];
    const float* Whh_e    = (const float*)d_in[7];
    const float* bhh_e    = (const float*)d_in[8];
    const float* Wih_d    = (const float*)d_in[9];
    const float* bih_d    = (const float*)d_in[10];
    const float* Whh_d    = (const float*)d_in[11];
    const float* bhh_d    = (const float*)d_in[12];
    const float* W_out    = (const float*)d_in[13];
    const float* b_out    = (const float*)d_in[14];
    float* out = (float*)d_out;

    int T = in_sizes[0] / (N_AG * 2);
    if (T > 16) T = 16;
    int npred = out_size / (N_AG * 2);

    setup_kernel<<<64, 256>>>(observed, T, W_pool, Wih_e, bih_e, Whh_e, bhh_e,
                              Wih_d, bih_d, Whh_d, bhh_d);
    main_kernel<<<NCTA, NTHR>>>(T, npred, W_pos, b_pos, b_pool, W_out, b_out, out);
}